// round 5
// baseline (speedup 1.0000x reference)
#include <cuda_runtime.h>
#include <cuda_bf16.h>
#include <cstdint>

#define NN   8192
#define DIN  512
#define DOUT 512
#define NP   576      // padded cols for agg GEMM: 512 features + 1 deg col + pad (9 tiles of 64)
#define A2K  1024     // [x | agg] concat width

// ---------------- scratch (__device__ globals; no allocations allowed) ----------------
__device__ unsigned char g_adj8[(size_t)NN * NN];      // adj as int8 {0,1}
__device__ signed char   g_xt0[(size_t)NP * NN];       // x^T padded, int8 limb0 (scale 2^-4)
__device__ signed char   g_xt1[(size_t)NP * NN];       // x^T padded, int8 limb1 (scale 2^-11)
__device__ float         g_C1[(size_t)NN * NP];        // mask @ [x|1]  (fp32)
__device__ __nv_bfloat16 g_a2_hi[(size_t)NN * A2K];    // [x | agg] hi  [8192][1024]
__device__ __nv_bfloat16 g_a2_lo[(size_t)NN * A2K];
__device__ __nv_bfloat16 g_ws_hi[DIN * DOUT], g_ws_lo[DIN * DOUT];
__device__ __nv_bfloat16 g_wnb_hi[DIN * DOUT], g_wnb_lo[DIN * DOUT];
__device__ __nv_bfloat16 g_wcT_hi[DOUT * 1024], g_wcT_lo[DOUT * 1024];   // W_comb^T [n=512][k=1024]
__device__ __nv_bfloat16 g_wabT_hi[DOUT * 1024], g_wabT_lo[DOUT * 1024]; // fused weights^T [512][1024]
__device__ float         g_bias[DOUT];

// ---------------- helpers ----------------
__device__ __forceinline__ uint32_t smem_u32(const void* p) {
    uint32_t a;
    asm("{ .reg .u64 t; cvta.to.shared.u64 t, %1; cvt.u32.u64 %0, t; }" : "=r"(a) : "l"(p));
    return a;
}
__device__ __forceinline__ void cp16(uint32_t dst, const void* src) {
    asm volatile("cp.async.cg.shared.global [%0], [%1], 16;" :: "r"(dst), "l"(src));
}
#define CP_COMMIT() asm volatile("cp.async.commit_group;" ::: "memory")
#define CP_WAIT1()  asm volatile("cp.async.wait_group 1;" ::: "memory")
#define CP_WAIT2()  asm volatile("cp.async.wait_group 2;" ::: "memory")

__device__ __forceinline__ void split2(float v, __nv_bfloat16& h, __nv_bfloat16& l) {
    h = __float2bfloat16(v);
    l = __float2bfloat16(v - __bfloat162float(h));
}

__device__ __forceinline__ void mma_bf16(float* d,
                                         uint32_t a0, uint32_t a1, uint32_t a2, uint32_t a3,
                                         uint32_t b0, uint32_t b1) {
    asm volatile(
        "mma.sync.aligned.m16n8k16.row.col.f32.bf16.bf16.f32 "
        "{%0,%1,%2,%3},{%4,%5,%6,%7},{%8,%9},{%0,%1,%2,%3};\n"
        : "+f"(d[0]), "+f"(d[1]), "+f"(d[2]), "+f"(d[3])
        : "r"(a0), "r"(a1), "r"(a2), "r"(a3), "r"(b0), "r"(b1));
}

__device__ __forceinline__ void imma8(int* c,
                                      uint32_t a0, uint32_t a1, uint32_t a2, uint32_t a3,
                                      uint32_t b0, uint32_t b1) {
    asm volatile(
        "mma.sync.aligned.m16n8k32.row.col.s32.s8.s8.s32 "
        "{%0,%1,%2,%3},{%4,%5,%6,%7},{%8,%9},{%0,%1,%2,%3};\n"
        : "+r"(c[0]), "+r"(c[1]), "+r"(c[2]), "+r"(c[3])
        : "r"(a0), "r"(a1), "r"(a2), "r"(a3), "r"(b0), "r"(b1));
}

// ---------------- prep kernels ----------------
// adj int32 -> int8 {0,1}, one uint4 (4 ints) -> 4 bytes per thread
__global__ void k_adj8(const int* __restrict__ adj) {
    size_t idx = (size_t)blockIdx.x * 256 + threadIdx.x;
    const uint4* a4 = reinterpret_cast<const uint4*>(adj);
    uint4 v = a4[idx];
    uint32_t w = (v.x ? 1u : 0u) | (v.y ? 0x100u : 0u) | (v.z ? 0x10000u : 0u) | (v.w ? 0x1000000u : 0u);
    reinterpret_cast<uint32_t*>(g_adj8)[idx] = w;
}

__global__ void k_split_w(const float* __restrict__ ws, const float* __restrict__ wn) {
    int idx = blockIdx.x * blockDim.x + threadIdx.x;
    if (idx < DIN * DOUT) {
        split2(ws[idx], g_ws_hi[idx], g_ws_lo[idx]);
        split2(wn[idx], g_wnb_hi[idx], g_wnb_lo[idx]);
    }
}

__global__ void k_transpose_wc(const float* __restrict__ wc) {
    __shared__ float t[32][33];
    int n0 = blockIdx.x * 32, r0 = blockIdx.y * 32;
    for (int ii = threadIdx.y; ii < 32; ii += 8)
        t[ii][threadIdx.x] = wc[(size_t)(r0 + ii) * DOUT + n0 + threadIdx.x];
    __syncthreads();
    for (int jj = threadIdx.y; jj < 32; jj += 8) {
        int n = n0 + jj, k = r0 + threadIdx.x;
        __nv_bfloat16 h, l;
        split2(t[threadIdx.x][jj], h, l);
        g_wcT_hi[(size_t)n * 1024 + k] = h;
        g_wcT_lo[(size_t)n * 1024 + k] = l;
    }
}

// x [8192][512] -> x^T padded int8 limbs [576][8192]; col 512 = ones (deg), rest 0
__global__ void k_build_xt8(const float* __restrict__ x) {
    __shared__ float t[32][33];
    int n0 = blockIdx.x * 32, i0 = blockIdx.y * 32;
    for (int ii = threadIdx.y; ii < 32; ii += 8) {
        int j = n0 + threadIdx.x;
        float v;
        if (j < DIN) v = x[(size_t)(i0 + ii) * DIN + j];
        else         v = (j == DIN) ? 1.0f : 0.0f;
        t[ii][threadIdx.x] = v;
    }
    __syncthreads();
    for (int jj = threadIdx.y; jj < 32; jj += 8) {
        int n = n0 + jj, k = i0 + threadIdx.x;
        float v = t[threadIdx.x][jj];
        int l0 = __float2int_rn(v * 16.0f);
        l0 = max(-127, min(127, l0));
        float r = v - (float)l0 * 0.0625f;
        int l1 = __float2int_rn(r * 2048.0f);
        l1 = max(-127, min(127, l1));
        g_xt0[(size_t)n * NN + k] = (signed char)l0;
        g_xt1[(size_t)n * NN + k] = (signed char)l1;
    }
}

__global__ void k_a2x(const float* __restrict__ x) {
    int idx = blockIdx.x * blockDim.x + threadIdx.x;
    if (idx < NN * DIN) {
        int i = idx >> 9, j = idx & 511;
        split2(x[idx], g_a2_hi[(size_t)i * A2K + j], g_a2_lo[(size_t)i * A2K + j]);
    }
}

__global__ void k_bias(const float* __restrict__ bs, const float* __restrict__ bn,
                       const float* __restrict__ bc, const float* __restrict__ wc) {
    int j = threadIdx.x;
    float s = bc[j];
    for (int k = 0; k < DIN; k++) {
        s += bs[k] * wc[(size_t)k * DOUT + j];
        s += bn[k] * wc[(size_t)(DIN + k) * DOUT + j];
    }
    g_bias[j] = s;
}

__global__ void k_epi() {
    int idx = blockIdx.x * blockDim.x + threadIdx.x;
    if (idx < NN * DIN) {
        int i = idx >> 9, j = idx & 511;
        float deg = g_C1[(size_t)i * NP + DIN];
        float r = 1.0f / fmaxf(deg, 1.0f);
        float v = g_C1[(size_t)i * NP + j] * r;
        split2(v, g_a2_hi[(size_t)i * A2K + 512 + j], g_a2_lo[(size_t)i * A2K + 512 + j]);
    }
}

// ================= int8 IMMA agg GEMM: C1[8192][576] = mask(adj) @ [x|1] =================
// block 128(M) x 64(N), BK=64; 256 threads = 8 warps (4M x 2N), warp tile 32x32.
// 2 int8 limbs for x; exact int32 accumulation; 4-stage cp.async pipeline.
// SMEM stage: A 128 rows x 20 words (80B, 64 int8 + pad) = 2560 w; B limb0/limb1 64x20 = 1280 w each.
#define AG_STW 5120
#define AG_SMEM (4 * AG_STW * 4)

__global__ void __launch_bounds__(256, 2) agg8() {
    extern __shared__ uint32_t sm[];
    uint32_t sb = smem_u32(sm);
    int tid = threadIdx.x, wid = tid >> 5, lane = tid & 31;
    int wm = wid >> 1, wn = wid & 1;
    int g = lane >> 2, q = lane & 3;
    int m0 = blockIdx.y * 128, n0 = blockIdx.x * 64;

    int acc0[2][4][4], acc1[2][4][4];
#pragma unroll
    for (int a = 0; a < 2; a++)
#pragma unroll
        for (int b = 0; b < 4; b++)
#pragma unroll
            for (int c = 0; c < 4; c++) { acc0[a][b][c] = 0; acc1[a][b][c] = 0; }

    // per-thread load roles (fixed)
    int arow0 = tid >> 2, ac0 = tid & 3;                 // A chunks 0..255
    int arow1 = (tid + 256) >> 2, ac1 = tid & 3;         // A chunks 256..511
    int brow = tid >> 2, bc = tid & 3;                   // B chunks 0..255 (rows 0..63)

    auto load_tile = [&](int kt, int s) {
        uint32_t base = sb + (uint32_t)(s * AG_STW) * 4;
        size_t koff = (size_t)kt * 64;
        cp16(base + (uint32_t)(arow0 * 20 + ac0 * 4) * 4,
             g_adj8 + (size_t)(m0 + arow0) * NN + koff + ac0 * 16);
        cp16(base + (uint32_t)(arow1 * 20 + ac1 * 4) * 4,
             g_adj8 + (size_t)(m0 + arow1) * NN + koff + ac1 * 16);
        cp16(base + (uint32_t)(2560 + brow * 20 + bc * 4) * 4,
             g_xt0 + (size_t)(n0 + brow) * NN + koff + bc * 16);
        cp16(base + (uint32_t)(3840 + brow * 20 + bc * 4) * 4,
             g_xt1 + (size_t)(n0 + brow) * NN + koff + bc * 16);
    };

    load_tile(0, 0); CP_COMMIT();
    load_tile(1, 1); CP_COMMIT();
    load_tile(2, 2); CP_COMMIT();

    for (int kt = 0; kt < 128; kt++) {
        int s = kt & 3;
        CP_WAIT2();
        __syncthreads();
        if (kt + 3 < 128) load_tile(kt + 3, (kt + 3) & 3);
        CP_COMMIT();

        const uint32_t* A  = sm + s * AG_STW;
        const uint32_t* B0 = A + 2560;
        const uint32_t* B1 = A + 3840;
#pragma unroll
        for (int ks = 0; ks < 2; ks++) {
            int kw = ks * 8 + q;
            uint32_t a[2][4];
#pragma unroll
            for (int im = 0; im < 2; im++) {
                int r = wm * 32 + im * 16 + g;
                a[im][0] = A[r * 20 + kw];
                a[im][1] = A[(r + 8) * 20 + kw];
                a[im][2] = A[r * 20 + kw + 4];
                a[im][3] = A[(r + 8) * 20 + kw + 4];
            }
#pragma unroll
            for (int inf = 0; inf < 4; inf++) {
                int n = wn * 32 + inf * 8 + g;
                uint32_t b00 = B0[n * 20 + kw], b01 = B0[n * 20 + kw + 4];
                uint32_t b10 = B1[n * 20 + kw], b11 = B1[n * 20 + kw + 4];
#pragma unroll
                for (int im = 0; im < 2; im++) {
                    imma8(acc0[im][inf], a[im][0], a[im][1], a[im][2], a[im][3], b00, b01);
                    imma8(acc1[im][inf], a[im][0], a[im][1], a[im][2], a[im][3], b10, b11);
                }
            }
        }
    }

    const float s0 = 0.0625f, s1 = 4.8828125e-4f;  // 2^-4, 2^-11
#pragma unroll
    for (int im = 0; im < 2; im++)
#pragma unroll
        for (int inf = 0; inf < 4; inf++) {
            int r = m0 + wm * 32 + im * 16 + g;
            int c = n0 + wn * 32 + inf * 8 + q * 2;
            float2 v01, v23;
            v01.x = (float)acc0[im][inf][0] * s0 + (float)acc1[im][inf][0] * s1;
            v01.y = (float)acc0[im][inf][1] * s0 + (float)acc1[im][inf][1] * s1;
            v23.x = (float)acc0[im][inf][2] * s0 + (float)acc1[im][inf][2] * s1;
            v23.y = (float)acc0[im][inf][3] * s0 + (float)acc1[im][inf][3] * s1;
            *reinterpret_cast<float2*>(g_C1 + (size_t)r * NP + c) = v01;
            *reinterpret_cast<float2*>(g_C1 + (size_t)(r + 8) * NP + c) = v23;
        }
}

// ---------------- split bf16 GEMM (legacy mma), 3-stage cp.async pipeline ----------------
// block 64x64, BK=64, 128 threads (4 warps: 2x2), warp tile 32x32
// mode 0: WabT[:, 0:512]    = (W_self @ Wc1)^T
// mode 1: WabT[:, 512:1024] = (W_nb  @ Wc2)^T
// mode 2: out = relu([x|agg] @ Wab + bias)
// SMEM stage: Ah/Al/Bh/Bl each 64 rows x 36 words = 2304 w; stage = 9216 w = 36864 B; 3 stages.
#define G2_STW 9216
#define G2_SMEM (3 * G2_STW * 4)

__global__ void __launch_bounds__(128) k_gemm2(int mode, float* __restrict__ out) {
    extern __shared__ uint32_t sm[];
    uint32_t sb = smem_u32(sm);

    const __nv_bfloat16 *ah, *al, *bh, *bl;
    int lda, ldb, NT, moff;
    if (mode == 0)      { ah = g_ws_hi;  al = g_ws_lo;  lda = 512;  bh = g_wcT_hi;       bl = g_wcT_lo;       ldb = 1024; NT = 8;  moff = 0;   }
    else if (mode == 1) { ah = g_wnb_hi; al = g_wnb_lo; lda = 512;  bh = g_wcT_hi + 512; bl = g_wcT_lo + 512; ldb = 1024; NT = 8;  moff = 512; }
    else                { ah = g_a2_hi;  al = g_a2_lo;  lda = 1024; bh = g_wabT_hi;      bl = g_wabT_lo;      ldb = 1024; NT = 16; moff = 0;   }

    int tid = threadIdx.x;
    int wid = tid >> 5, lane = tid & 31;
    int wm = wid >> 1, wn = wid & 1;
    int g = lane >> 2, tq = lane & 3;
    int m0 = blockIdx.y * 64, n0 = blockIdx.x * 64;

    float acc[2][4][4];
#pragma unroll
    for (int a = 0; a < 2; a++)
#pragma unroll
        for (int b = 0; b < 4; b++)
#pragma unroll
            for (int c = 0; c < 4; c++) acc[a][b][c] = 0.0f;

    auto load_tile = [&](int it, int s) {
        uint32_t base = sb + (uint32_t)(s * G2_STW) * 4;
#pragma unroll
        for (int i = 0; i < 4; i++) {
            int linear = tid + i * 128;
            int row = linear >> 3, c8 = linear & 7;
            uint32_t w = (uint32_t)(row * 36 + c8 * 4) * 4;
            size_t ao = (size_t)(m0 + row) * lda + it * 64 + c8 * 8;
            size_t bo = (size_t)(n0 + row) * ldb + it * 64 + c8 * 8;
            cp16(base + w,                 ah + ao);
            cp16(base + 2304 * 4 + w,      al + ao);
            cp16(base + 4608 * 4 + w,      bh + bo);
            cp16(base + 6912 * 4 + w,      bl + bo);
        }
    };

    load_tile(0, 0); CP_COMMIT();
    load_tile(1, 1); CP_COMMIT();

    int sc = 0;
    for (int it = 0; it < NT; it++) {
        CP_WAIT1();
        __syncthreads();
        if (it + 2 < NT) {
            int sp = sc + 2; if (sp >= 3) sp -= 3;
            load_tile(it + 2, sp);
        }
        CP_COMMIT();

        const uint32_t* Ah = sm + sc * G2_STW;
        const uint32_t* Al = Ah + 2304;
        const uint32_t* Bh = Ah + 4608;
        const uint32_t* Bl = Ah + 6912;

#pragma unroll
        for (int ks = 0; ks < 4; ks++) {
            int kw = ks * 8;
            uint32_t aHi[2][4], aLo[2][4];
#pragma unroll
            for (int im = 0; im < 2; im++) {
                int r = wm * 32 + im * 16 + g;
                aHi[im][0] = Ah[r * 36 + kw + tq];
                aHi[im][1] = Ah[(r + 8) * 36 + kw + tq];
                aHi[im][2] = Ah[r * 36 + kw + tq + 4];
                aHi[im][3] = Ah[(r + 8) * 36 + kw + tq + 4];
                aLo[im][0] = Al[r * 36 + kw + tq];
                aLo[im][1] = Al[(r + 8) * 36 + kw + tq];
                aLo[im][2] = Al[r * 36 + kw + tq + 4];
                aLo[im][3] = Al[(r + 8) * 36 + kw + tq + 4];
            }
#pragma unroll
            for (int in = 0; in < 4; in++) {
                int rn = wn * 32 + in * 8 + g;
                uint32_t bh0 = Bh[rn * 36 + kw + tq], bh1 = Bh[rn * 36 + kw + tq + 4];
                uint32_t bl0 = Bl[rn * 36 + kw + tq], bl1 = Bl[rn * 36 + kw + tq + 4];
#pragma unroll
                for (int im = 0; im < 2; im++) {
                    mma_bf16(acc[im][in], aHi[im][0], aHi[im][1], aHi[im][2], aHi[im][3], bh0, bh1);
                    mma_bf16(acc[im][in], aHi[im][0], aHi[im][1], aHi[im][2], aHi[im][3], bl0, bl1);
                    mma_bf16(acc[im][in], aLo[im][0], aLo[im][1], aLo[im][2], aLo[im][3], bh0, bh1);
                }
            }
        }
        sc++; if (sc == 3) sc = 0;
    }

#pragma unroll
    for (int im = 0; im < 2; im++)
#pragma unroll
        for (int in = 0; in < 4; in++) {
            int rr = m0 + wm * 32 + im * 16 + g;
            int cc = n0 + wn * 32 + in * 8 + tq * 2;
            if (mode < 2) {
#pragma unroll
                for (int e = 0; e < 4; e++) {
                    int r = rr + (e >> 1) * 8;
                    int c = cc + (e & 1);
                    __nv_bfloat16 h, l;
                    split2(acc[im][in][e], h, l);
                    g_wabT_hi[(size_t)c * 1024 + moff + r] = h;
                    g_wabT_lo[(size_t)c * 1024 + moff + r] = l;
                }
            } else {
#pragma unroll
                for (int e = 0; e < 4; e++) {
                    int r = rr + (e >> 1) * 8;
                    int c = cc + (e & 1);
                    float v = acc[im][in][e] + g_bias[c];
                    out[(size_t)r * DOUT + c] = fmaxf(v, 0.0f);
                }
            }
        }
}

// ---------------- launch ----------------
extern "C" void kernel_launch(void* const* d_in, const int* in_sizes, int n_in,
                              void* d_out, int out_size) {
    const float* x      = (const float*)d_in[0];
    const int*   adj    = (const int*)d_in[1];
    const float* W_self = (const float*)d_in[2];
    const float* b_self = (const float*)d_in[3];
    const float* W_nb   = (const float*)d_in[4];
    const float* b_nb   = (const float*)d_in[5];
    const float* W_comb = (const float*)d_in[6];
    const float* b_comb = (const float*)d_in[7];
    float* out = (float*)d_out;

    cudaFuncSetAttribute(agg8, cudaFuncAttributeMaxDynamicSharedMemorySize, AG_SMEM);
    cudaFuncSetAttribute(k_gemm2, cudaFuncAttributeMaxDynamicSharedMemorySize, G2_SMEM);

    // prep (all independent of agg result)
    k_adj8<<<NN * NN / 4 / 256, 256>>>(adj);
    k_split_w<<<(DIN * DOUT + 255) / 256, 256>>>(W_self, W_nb);
    k_transpose_wc<<<dim3(16, 32), dim3(32, 8)>>>(W_comb);
    k_build_xt8<<<dim3(NP / 32, NN / 32), dim3(32, 8)>>>(x);
    k_a2x<<<(NN * DIN + 255) / 256, 256>>>(x);
    k_bias<<<1, DOUT>>>(b_self, b_nb, b_comb, W_comb);
    // fused weights (tiny)
    k_gemm2<<<dim3(8, 8), 128, G2_SMEM>>>(0, nullptr);
    k_gemm2<<<dim3(8, 8), 128, G2_SMEM>>>(1, nullptr);
    // neighbor aggregation (dominant GEMM, int8 IMMA) + epilogue
    agg8<<<dim3(NP / 64, NN / 128), 256, AG_SMEM>>>();
    k_epi<<<(NN * DIN + 255) / 256, 256>>>();
    // final fused layer
    k_gemm2<<<dim3(DOUT / 64, NN / 64), 128, G2_SMEM>>>(2, out);
}